// round 12
// baseline (speedup 1.0000x reference)
#include <cuda_runtime.h>
#include <cuda_fp16.h>

#define NN 50000
#define EE 1600000
#define SCAN_B 256
#define NBLK ((NN + SCAN_B - 1) / SCAN_B)   // 196

// Scratch (device globals; zero-initialized at module load)
__device__ __align__(16) float4 g_h [NN * 32];     // h = (1+eps)*x + agg
__device__ __align__(16) float4 g_h1[NN * 32];     // h @ W1 + b1
__device__ float g_sum[128];
__device__ float g_sumsq[128];
__device__ __align__(16) __half g_ch[125 * 128];   // combo table in fp16 (32KB, L1-resident)
__device__ __align__(16) uint2 g_xh[NN * 32];      // x in fp16
__device__ int  g_deg[NN];                         // zeroed by agg_kernel after use
__device__ int  g_off[NN];
__device__ int  g_cur[NN];
__device__ int  g_bsum[NBLK];
__device__ int  g_boff[NBLK];
__device__ int  g_scan_done;                       // reset by fused_setup each call
__device__ volatile int g_ready;                   // reset by fused_setup each call
__device__ int  g_csr[EE];                         // packed (src<<7)|code, grouped by dst

// ---------------------------------------------------------------------------
// Fused setup: convert x -> fp16, build fp16 combo table, histogram dst,
// reset single-pass-scan flags. NN*32 == EE == 1.6M, one grid covers all.
// ---------------------------------------------------------------------------
__global__ void fused_setup(const float4* __restrict__ x4,
                            const float*  __restrict__ be,
                            const int*    __restrict__ dst) {
    int i = blockIdx.x * blockDim.x + threadIdx.x;
    if (i == 0) { g_scan_done = 0; g_ready = 0; }
    if (i < NN * 32) {
        float4 v = x4[i];
        __half2 lo = __float22half2_rn(make_float2(v.x, v.y));
        __half2 hi = __float22half2_rn(make_float2(v.z, v.w));
        uint2 p;
        p.x = *(unsigned*)&lo;
        p.y = *(unsigned*)&hi;
        g_xh[i] = p;
    }
    if (i < 125 * 128) {
        int c = i >> 7, t = i & 127;
        float s = be[(c / 25) * 128 + t]
                + be[(5 + (c / 5) % 5) * 128 + t]
                + be[(10 + c % 5) * 128 + t];
        g_ch[i] = __float2half_rn(s);
    }
    if (i < EE) atomicAdd(&g_deg[dst[i]], 1);
}

// ---------------------------------------------------------------------------
// Single-pass chip-wide exclusive scan of g_deg -> g_off / g_cur.
// 196 blocks all co-resident (148 SMs) so the last-block spin cannot deadlock.
// Also zeroes the BN stat accumulators (block 0).
// ---------------------------------------------------------------------------
__global__ void scan_kernel() {
    __shared__ int ws[8];
    __shared__ int sh2[SCAN_B];
    __shared__ bool is_last;
    int t = threadIdx.x, lane = t & 31, w = t >> 5, b = blockIdx.x;

    if (b == 0 && t < 128) { g_sum[t] = 0.f; g_sumsq[t] = 0.f; }

    int i = b * SCAN_B + t;
    int v = (i < NN) ? g_deg[i] : 0;

    int s = v;
#pragma unroll
    for (int o = 1; o < 32; o <<= 1) {
        int u = __shfl_up_sync(0xffffffffu, s, o);
        if (lane >= o) s += u;
    }
    if (lane == 31) ws[w] = s;
    __syncthreads();
    if (t < 8) {
        int a = ws[t];
#pragma unroll
        for (int o = 1; o < 8; o <<= 1) {
            int u = __shfl_up_sync(0xffu, a, o);
            if (t >= o) a += u;
        }
        ws[t] = a;
    }
    __syncthreads();

    if (t == 0) {
        g_bsum[b] = ws[7];
        __threadfence();
        int done = atomicAdd(&g_scan_done, 1);
        is_last = (done == NBLK - 1);
    }
    __syncthreads();

    if (is_last) {
        int val = (t < NBLK) ? g_bsum[t] : 0;
        sh2[t] = val;
        __syncthreads();
        for (int o = 1; o < SCAN_B; o <<= 1) {
            int u = (t >= o) ? sh2[t - o] : 0;
            __syncthreads();
            sh2[t] += u;
            __syncthreads();
        }
        if (t < NBLK) g_boff[t] = sh2[t] - val;
        __threadfence();
        __syncthreads();
        if (t == 0) g_ready = 1;
    }

    if (t == 0) { while (g_ready == 0) { } }
    __syncthreads();
    __threadfence();

    int ex = s - v + (w ? ws[w - 1] : 0) + g_boff[b];
    if (i < NN) { g_off[i] = ex; g_cur[i] = ex; }
}

__global__ void scatter_kernel(const int* __restrict__ src,
                               const int* __restrict__ dst,
                               const int* __restrict__ ea) {
    int e = blockIdx.x * blockDim.x + threadIdx.x;
    if (e >= EE) return;
    int d = dst[e];
    int code = (ea[e * 3 + 0] * 5 + ea[e * 3 + 1]) * 5 + ea[e * 3 + 2];
    int pos = atomicAdd(&g_cur[d], 1);
    g_csr[pos] = (src[e] << 7) | code;   // src < 2^16, code < 2^7
}

// ---------------------------------------------------------------------------
// Aggregation: two nodes per warp + double-buffered software pipeline:
// while consuming batch i (8 edges), batch i+1's CSR words and x-gathers are
// already in flight in a second set of named scalars. Combo loads (32KB
// L1-resident table) issue in the consume phase. fp32 accumulation.
// ---------------------------------------------------------------------------
__device__ __forceinline__ void acc_edge(float4& acc, int p, int lane) {
    int s    = p >> 7;
    int code = p & 127;
    uint2 xv = g_xh[s * 32 + lane];
    uint2 cv = ((const uint2*)g_ch)[code * 32 + lane];
    __half2 z = __float2half2_rn(0.f);
    __half2 m0 = __hmax2(__hadd2(*(__half2*)&xv.x, *(__half2*)&cv.x), z);
    __half2 m1 = __hmax2(__hadd2(*(__half2*)&xv.y, *(__half2*)&cv.y), z);
    float2 f0 = __half22float2(m0);
    float2 f1 = __half22float2(m1);
    acc.x += f0.x; acc.y += f0.y; acc.z += f1.x; acc.w += f1.y;
}

__device__ __forceinline__ void hconsume(float4& acc, uint2 xv, uint2 cv) {
    __half2 z = __float2half2_rn(0.f);
    __half2 m0 = __hmax2(__hadd2(*(__half2*)&xv.x, *(__half2*)&cv.x), z);
    __half2 m1 = __hmax2(__hadd2(*(__half2*)&xv.y, *(__half2*)&cv.y), z);
    float2 f0 = __half22float2(m0);
    float2 f1 = __half22float2(m1);
    acc.x += f0.x; acc.y += f0.y; acc.z += f1.x; acc.w += f1.y;
}

__global__ void __launch_bounds__(256, 2)
agg_kernel(const float4* __restrict__ x4, const float* __restrict__ eps) {
    int gt   = blockIdx.x * blockDim.x + threadIdx.x;
    int wrp  = gt >> 5;
    int lane = gt & 31;
    int v0   = wrp * 2;
    if (v0 >= NN) return;
    int v1 = v0 + 1;
    bool has1 = (v1 < NN);

    int s0 = g_off[v0];
    int d0 = g_deg[v0];
    int s1 = has1 ? g_off[v1] : 0;
    int d1 = has1 ? g_deg[v1] : 0;
    if (lane == 0) {
        g_deg[v0] = 0;                 // reset for next kernel_launch call
        if (has1) g_deg[v1] = 0;
    }

    const uint2* ch2 = (const uint2*)g_ch;
    float4 a0 = make_float4(0, 0, 0, 0);
    float4 a1 = make_float4(0, 0, 0, 0);

    int nIt = (d0 < d1 ? d0 : d1) >> 2;   // fused batches of 4+4 edges
    int i0 = nIt * 4, i1 = nIt * 4;

    if (nIt > 0) {
        // ---- prologue: issue batch 0 (CSR + x-gathers) ----
        int q0 = g_csr[s0], q1 = g_csr[s0 + 1], q2 = g_csr[s0 + 2], q3 = g_csr[s0 + 3];
        int q4 = g_csr[s1], q5 = g_csr[s1 + 1], q6 = g_csr[s1 + 2], q7 = g_csr[s1 + 3];
        uint2 x0 = g_xh[(q0 >> 7) * 32 + lane];
        uint2 x1 = g_xh[(q1 >> 7) * 32 + lane];
        uint2 x2 = g_xh[(q2 >> 7) * 32 + lane];
        uint2 x3 = g_xh[(q3 >> 7) * 32 + lane];
        uint2 x4v = g_xh[(q4 >> 7) * 32 + lane];
        uint2 x5 = g_xh[(q5 >> 7) * 32 + lane];
        uint2 x6 = g_xh[(q6 >> 7) * 32 + lane];
        uint2 x7 = g_xh[(q7 >> 7) * 32 + lane];

        for (int it = 1; it < nIt; it++) {
            int b0 = s0 + it * 4, b1 = s1 + it * 4;
            // ---- issue batch it (next) ----
            int n0 = g_csr[b0], n1 = g_csr[b0 + 1], n2 = g_csr[b0 + 2], n3 = g_csr[b0 + 3];
            int n4 = g_csr[b1], n5 = g_csr[b1 + 1], n6 = g_csr[b1 + 2], n7 = g_csr[b1 + 3];
            uint2 y0 = g_xh[(n0 >> 7) * 32 + lane];
            uint2 y1 = g_xh[(n1 >> 7) * 32 + lane];
            uint2 y2 = g_xh[(n2 >> 7) * 32 + lane];
            uint2 y3 = g_xh[(n3 >> 7) * 32 + lane];
            uint2 y4 = g_xh[(n4 >> 7) * 32 + lane];
            uint2 y5 = g_xh[(n5 >> 7) * 32 + lane];
            uint2 y6 = g_xh[(n6 >> 7) * 32 + lane];
            uint2 y7 = g_xh[(n7 >> 7) * 32 + lane];

            // ---- consume batch it-1 (combo loads hit L1) ----
            hconsume(a0, x0, ch2[(q0 & 127) * 32 + lane]);
            hconsume(a0, x1, ch2[(q1 & 127) * 32 + lane]);
            hconsume(a0, x2, ch2[(q2 & 127) * 32 + lane]);
            hconsume(a0, x3, ch2[(q3 & 127) * 32 + lane]);
            hconsume(a1, x4v, ch2[(q4 & 127) * 32 + lane]);
            hconsume(a1, x5, ch2[(q5 & 127) * 32 + lane]);
            hconsume(a1, x6, ch2[(q6 & 127) * 32 + lane]);
            hconsume(a1, x7, ch2[(q7 & 127) * 32 + lane]);

            // ---- rotate ----
            q0 = n0; q1 = n1; q2 = n2; q3 = n3; q4 = n4; q5 = n5; q6 = n6; q7 = n7;
            x0 = y0; x1 = y1; x2 = y2; x3 = y3; x4v = y4; x5 = y5; x6 = y6; x7 = y7;
        }
        // ---- epilogue: consume last batch ----
        hconsume(a0, x0, ch2[(q0 & 127) * 32 + lane]);
        hconsume(a0, x1, ch2[(q1 & 127) * 32 + lane]);
        hconsume(a0, x2, ch2[(q2 & 127) * 32 + lane]);
        hconsume(a0, x3, ch2[(q3 & 127) * 32 + lane]);
        hconsume(a1, x4v, ch2[(q4 & 127) * 32 + lane]);
        hconsume(a1, x5, ch2[(q5 & 127) * 32 + lane]);
        hconsume(a1, x6, ch2[(q6 & 127) * 32 + lane]);
        hconsume(a1, x7, ch2[(q7 & 127) * 32 + lane]);
    }

    // Tails: simple per-edge loops
    for (; i0 < d0; i0++) acc_edge(a0, g_csr[s0 + i0], lane);
    for (; i1 < d1; i1++) acc_edge(a1, g_csr[s1 + i1], lane);

    float c = 1.0f + *eps;
    {
        float4 xv = x4[v0 * 32 + lane];
        float4 h;
        h.x = fmaf(c, xv.x, a0.x);
        h.y = fmaf(c, xv.y, a0.y);
        h.z = fmaf(c, xv.z, a0.z);
        h.w = fmaf(c, xv.w, a0.w);
        g_h[v0 * 32 + lane] = h;
    }
    if (has1) {
        float4 xv = x4[v1 * 32 + lane];
        float4 h;
        h.x = fmaf(c, xv.x, a1.x);
        h.y = fmaf(c, xv.y, a1.y);
        h.z = fmaf(c, xv.z, a1.z);
        h.w = fmaf(c, xv.w, a1.w);
        g_h[v1 * 32 + lane] = h;
    }
}

// ---------------------------------------------------------------------------
// GEMM via fma.rn.f32x2, even/odd-k packed accumulators (unchanged).
// ---------------------------------------------------------------------------
#define WT_PITCH 132
#define WT_FLOATS (128 * WT_PITCH)
#define XS_OFF_B  (WT_FLOATS * 4)
#define GEMM_SMEM (XS_OFF_B + 64 * 128 * 4)

__device__ __forceinline__ float2 unpk(unsigned long long v) {
    float2 r;
    asm("mov.b64 {%0, %1}, %2;" : "=f"(r.x), "=f"(r.y) : "l"(v));
    return r;
}

template <int PASS>
__global__ __launch_bounds__(128)
void gemm_kernel(const float* __restrict__ Wg,
                 const float* __restrict__ bias,
                 float*       __restrict__ outp,
                 const float* __restrict__ gamma,
                 const float* __restrict__ beta) {
    extern __shared__ float sh[];
    __shared__ __align__(16) float ssum[128];
    __shared__ __align__(16) float ssq[128];
    __shared__ __align__(16) float sa[128];
    __shared__ __align__(16) float sb[128];

    const int t    = threadIdx.x;
    const int lane = t & 31;
    const int wrp  = t >> 5;

    if (PASS == 1) { ssum[t] = 0.f; ssq[t] = 0.f; }
    if (PASS == 2) {
        const float inv = 1.0f / (float)NN;
        float mean = g_sum[t] * inv;
        float var  = g_sumsq[t] * inv - mean * mean;
        float s = gamma[t] * rsqrtf(var + 1e-5f);
        sa[t] = s;
        sb[t] = beta[t] - mean * s;
    }
    __syncthreads();

    // Stage W transposed: Wt[c][k] = W[k][c], pitch 132
    {
        const int c = t;
        for (int g = 0; g < 32; g++) {
            int k0 = g * 4;
            float w0 = Wg[(k0 + 0) * 128 + c];
            float w1 = Wg[(k0 + 1) * 128 + c];
            float w2 = Wg[(k0 + 2) * 128 + c];
            float w3 = Wg[(k0 + 3) * 128 + c];
            *(float4*)&sh[c * WT_PITCH + k0] = make_float4(w0, w1, w2, w3);
        }
    }

    const float4* in4 = (PASS == 1) ? (const float4*)g_h : (const float4*)g_h1;
    float* xs = sh + WT_FLOATS;
    const int rowbase = blockIdx.x * 64;
#pragma unroll
    for (int j = 0; j < 16; j++) {
        int p = t + j * 128;
        int row = p >> 5, cp = p & 31;
        int gr = rowbase + row;
        float4 v = make_float4(0, 0, 0, 0);
        if (gr < NN) v = in4[gr * 32 + cp];
        if (PASS == 2) {
            float4 a = *(const float4*)&sa[cp * 4];
            float4 b = *(const float4*)&sb[cp * 4];
            v.x = fmaxf(fmaf(v.x, a.x, b.x), 0.f);
            v.y = fmaxf(fmaf(v.y, a.y, b.y), 0.f);
            v.z = fmaxf(fmaf(v.z, a.z, b.z), 0.f);
            v.w = fmaxf(fmaf(v.w, a.w, b.w), 0.f);
        }
        *(float4*)&xs[row * 128 + cp * 4] = v;
    }
    __syncthreads();

    float* out_f = (PASS == 1) ? (float*)g_h1 : outp;

    float bv[4];
#pragma unroll
    for (int cc = 0; cc < 4; cc++) bv[cc] = bias[lane + 32 * cc];

    const unsigned shb = (unsigned)__cvta_generic_to_shared(sh);
    unsigned wb[4];
#pragma unroll
    for (int cc = 0; cc < 4; cc++) wb[cc] = shb + (unsigned)((lane + 32 * cc) * WT_PITCH) * 4u;
    const unsigned xsb = shb + XS_OFF_B;

    float ts[4] = {0, 0, 0, 0};
    float tq[4] = {0, 0, 0, 0};

    for (int half = 0; half < 2; half++) {
        const int r0 = half * 32 + wrp * 8;
        unsigned xr[8];
#pragma unroll
        for (int r = 0; r < 8; r++) xr[r] = xsb + (unsigned)((r0 + r) * 128) * 4u;

        unsigned long long acc[8][4];
#pragma unroll
        for (int r = 0; r < 8; r++)
#pragma unroll
            for (int cc = 0; cc < 4; cc++) acc[r][cc] = 0ULL;

#pragma unroll 4
        for (int k = 0; k < 128; k += 4) {
            unsigned long long w01[4], w23[4];
#pragma unroll
            for (int cc = 0; cc < 4; cc++)
                asm("ld.shared.v2.b64 {%0, %1}, [%2];"
                    : "=l"(w01[cc]), "=l"(w23[cc]) : "r"(wb[cc] + (unsigned)(k * 4)));
#pragma unroll
            for (int r = 0; r < 8; r++) {
                unsigned long long x01, x23;
                asm("ld.shared.v2.b64 {%0, %1}, [%2];"
                    : "=l"(x01), "=l"(x23) : "r"(xr[r] + (unsigned)(k * 4)));
#pragma unroll
                for (int cc = 0; cc < 4; cc++) {
                    asm("fma.rn.f32x2 %0, %1, %2, %0;" : "+l"(acc[r][cc]) : "l"(x01), "l"(w01[cc]));
                    asm("fma.rn.f32x2 %0, %1, %2, %0;" : "+l"(acc[r][cc]) : "l"(x23), "l"(w23[cc]));
                }
            }
        }

#pragma unroll
        for (int r = 0; r < 8; r++) {
            int gr = rowbase + r0 + r;
            if (gr < NN) {
#pragma unroll
                for (int cc = 0; cc < 4; cc++) {
                    float2 p = unpk(acc[r][cc]);
                    float o = p.x + p.y + bv[cc];
                    out_f[gr * 128 + lane + 32 * cc] = o;
                    if (PASS == 1) { ts[cc] += o; tq[cc] += o * o; }
                }
            }
        }
    }

    if (PASS == 1) {
#pragma unroll
        for (int cc = 0; cc < 4; cc++) {
            atomicAdd(&ssum[lane + 32 * cc], ts[cc]);
            atomicAdd(&ssq [lane + 32 * cc], tq[cc]);
        }
        __syncthreads();
        atomicAdd(&g_sum[t],   ssum[t]);
        atomicAdd(&g_sumsq[t], ssq[t]);
    }
}

// ---------------------------------------------------------------------------
extern "C" void kernel_launch(void* const* d_in, const int* in_sizes, int n_in,
                              void* d_out, int out_size) {
    const float* x     = (const float*)d_in[0];
    const int*   ea    = (const int*)  d_in[1];
    const int*   src   = (const int*)  d_in[2];
    const int*   dst   = (const int*)  d_in[3];
    const float* bond  = (const float*)d_in[4];
    const float* eps   = (const float*)d_in[5];
    const float* W1    = (const float*)d_in[6];
    const float* b1    = (const float*)d_in[7];
    const float* gamma = (const float*)d_in[8];
    const float* beta  = (const float*)d_in[9];
    const float* W2    = (const float*)d_in[10];
    const float* b2    = (const float*)d_in[11];

    cudaFuncSetAttribute(gemm_kernel<1>, cudaFuncAttributeMaxDynamicSharedMemorySize, GEMM_SMEM);
    cudaFuncSetAttribute(gemm_kernel<2>, cudaFuncAttributeMaxDynamicSharedMemorySize, GEMM_SMEM);

    fused_setup<<<(NN * 32 + 255) / 256, 256>>>((const float4*)x, bond, dst);
    scan_kernel<<<NBLK, SCAN_B>>>();
    scatter_kernel<<<(EE + 255) / 256, 256>>>(src, dst, ea);
    // 2 nodes per warp -> NN/2 warps -> 8 warps per 256-thread block
    agg_kernel<<<(NN / 2 + 7) / 8, 256>>>((const float4*)x, eps);
    gemm_kernel<1><<<(NN + 63) / 64, 128, GEMM_SMEM>>>(W1, b1, nullptr, nullptr, nullptr);
    gemm_kernel<2><<<(NN + 63) / 64, 128, GEMM_SMEM>>>(W2, b2, (float*)d_out, gamma, beta);
}

// round 13
// speedup vs baseline: 1.1890x; 1.1890x over previous
#include <cuda_runtime.h>
#include <cuda_fp16.h>

#define NN 50000
#define EE 1600000
#define SCAN_B 256
#define NBLK ((NN + SCAN_B - 1) / SCAN_B)   // 196
#define CHUNK 128                            // edges per warp in agg
#define PF 8                                 // edges per pipeline batch
#define NB (CHUNK / PF)                      // 16 batches
#define NWRP (EE / CHUNK)                    // 12500 (exact)

// Scratch (device globals; zero-initialized at module load)
__device__ __align__(16) float4 g_h [NN * 32];     // (1+eps)x preload, RED-accumulated
__device__ __align__(16) float4 g_h1[NN * 32];     // h @ W1 + b1
__device__ float g_sum[128];
__device__ float g_sumsq[128];
__device__ __align__(16) __half g_ch[125 * 128];   // combo table fp16 (32KB, L1-hot)
__device__ __align__(16) uint2 g_xh[NN * 32];      // x in fp16
__device__ int  g_deg[NN];                         // zeroed by scan_kernel after use
__device__ int  g_off[NN];
__device__ int  g_cur[NN];
__device__ int  g_bsum[NBLK];
__device__ int  g_boff[NBLK];
__device__ int  g_scan_done;                       // reset by fused_setup each call
__device__ volatile int g_ready;                   // reset by fused_setup each call
__device__ __align__(16) int2 g_csr2[EE];          // {src<<7|code, dst} grouped by dst

// ---------------------------------------------------------------------------
// Fused setup: x->fp16, g_h=(1+eps)x, combo table, dst histogram, flag reset.
// ---------------------------------------------------------------------------
__global__ void fused_setup(const float4* __restrict__ x4,
                            const float*  __restrict__ be,
                            const int*    __restrict__ dst,
                            const float*  __restrict__ eps) {
    int i = blockIdx.x * blockDim.x + threadIdx.x;
    if (i == 0) { g_scan_done = 0; g_ready = 0; }
    if (i < NN * 32) {
        float4 v = x4[i];
        __half2 lo = __float22half2_rn(make_float2(v.x, v.y));
        __half2 hi = __float22half2_rn(make_float2(v.z, v.w));
        uint2 p;
        p.x = *(unsigned*)&lo;
        p.y = *(unsigned*)&hi;
        g_xh[i] = p;
        float c = 1.0f + *eps;
        g_h[i] = make_float4(c * v.x, c * v.y, c * v.z, c * v.w);
    }
    if (i < 125 * 128) {
        int c = i >> 7, t = i & 127;
        float s = be[(c / 25) * 128 + t]
                + be[(5 + (c / 5) % 5) * 128 + t]
                + be[(10 + c % 5) * 128 + t];
        g_ch[i] = __float2half_rn(s);
    }
    if (i < EE) atomicAdd(&g_deg[dst[i]], 1);
}

// ---------------------------------------------------------------------------
// Single-pass chip-wide exclusive scan of g_deg -> g_off / g_cur; zeroes
// g_deg for the next call and the BN stat accumulators (block 0).
// ---------------------------------------------------------------------------
__global__ void scan_kernel() {
    __shared__ int ws[8];
    __shared__ int sh2[SCAN_B];
    __shared__ bool is_last;
    int t = threadIdx.x, lane = t & 31, w = t >> 5, b = blockIdx.x;

    if (b == 0 && t < 128) { g_sum[t] = 0.f; g_sumsq[t] = 0.f; }

    int i = b * SCAN_B + t;
    int v = (i < NN) ? g_deg[i] : 0;
    if (i < NN) g_deg[i] = 0;          // reset for next kernel_launch call

    int s = v;
#pragma unroll
    for (int o = 1; o < 32; o <<= 1) {
        int u = __shfl_up_sync(0xffffffffu, s, o);
        if (lane >= o) s += u;
    }
    if (lane == 31) ws[w] = s;
    __syncthreads();
    if (t < 8) {
        int a = ws[t];
#pragma unroll
        for (int o = 1; o < 8; o <<= 1) {
            int u = __shfl_up_sync(0xffu, a, o);
            if (t >= o) a += u;
        }
        ws[t] = a;
    }
    __syncthreads();

    if (t == 0) {
        g_bsum[b] = ws[7];
        __threadfence();
        int done = atomicAdd(&g_scan_done, 1);
        is_last = (done == NBLK - 1);
    }
    __syncthreads();

    if (is_last) {
        int val = (t < NBLK) ? g_bsum[t] : 0;
        sh2[t] = val;
        __syncthreads();
        for (int o = 1; o < SCAN_B; o <<= 1) {
            int u = (t >= o) ? sh2[t - o] : 0;
            __syncthreads();
            sh2[t] += u;
            __syncthreads();
        }
        if (t < NBLK) g_boff[t] = sh2[t] - val;
        __threadfence();
        __syncthreads();
        if (t == 0) g_ready = 1;
    }

    if (t == 0) { while (g_ready == 0) { } }
    __syncthreads();
    __threadfence();

    int ex = s - v + (w ? ws[w - 1] : 0) + g_boff[b];
    if (i < NN) { g_off[i] = ex; g_cur[i] = ex; }
}

__global__ void scatter_kernel(const int* __restrict__ src,
                               const int* __restrict__ dst,
                               const int* __restrict__ ea) {
    int e = blockIdx.x * blockDim.x + threadIdx.x;
    if (e >= EE) return;
    int d = dst[e];
    int code = (ea[e * 3 + 0] * 5 + ea[e * 3 + 1]) * 5 + ea[e * 3 + 2];
    int pos = atomicAdd(&g_cur[d], 1);
    g_csr2[pos] = make_int2((src[e] << 7) | code, d);
}

// ---------------------------------------------------------------------------
// Aggregation: one warp per 128-edge CSR chunk. 3-stage cp.async pipeline
// gathers x[src] into smem (zero register cost per in-flight byte); combo
// loads hit L1; dst-boundary flush via float4 atomicAdd (CSR is dst-sorted,
// so ~1 RED per node per chunk). Batch metadata lane-distributed + shfl.
// ---------------------------------------------------------------------------
#define CP_ASYNC8(sa, ga) \
    asm volatile("cp.async.ca.shared.global [%0], [%1], 8;" :: "r"(sa), "l"(ga))
#define CP_COMMIT() asm volatile("cp.async.commit_group;" ::: "memory")
#define CP_WAIT(n)  asm volatile("cp.async.wait_group " #n ";" ::: "memory")

__device__ __forceinline__ void issue_batch(int ebase, int lane, uint2* sbuf, int2& qn) {
    qn = g_csr2[ebase + (lane & 7)];
#pragma unroll
    for (int j = 0; j < PF; j++) {
        int sx = __shfl_sync(0xffffffffu, qn.x, j) >> 7;
        unsigned sa = (unsigned)__cvta_generic_to_shared(&sbuf[j * 32 + lane]);
        CP_ASYNC8(sa, &g_xh[sx * 32 + lane]);
    }
    CP_COMMIT();
}

__device__ __forceinline__ void consume_batch(int lane, const uint2* sbuf, int2 qc,
                                              float4& acc, int& cur) {
    const uint2* ch2 = (const uint2*)g_ch;
    const __half2 z = __float2half2_rn(0.f);
#pragma unroll
    for (int j = 0; j < PF; j++) {
        int wv = __shfl_sync(0xffffffffu, qc.x, j);
        int d  = __shfl_sync(0xffffffffu, qc.y, j);
        uint2 xv = sbuf[j * 32 + lane];
        uint2 cv = ch2[(wv & 127) * 32 + lane];
        __half2 m0 = __hmax2(__hadd2(*(__half2*)&xv.x, *(__half2*)&cv.x), z);
        __half2 m1 = __hmax2(__hadd2(*(__half2*)&xv.y, *(__half2*)&cv.y), z);
        float2 f0 = __half22float2(m0);
        float2 f1 = __half22float2(m1);
        if (d != cur) {
            if (cur >= 0) atomicAdd(&((float4*)g_h)[cur * 32 + lane], acc);
            cur = d;
            acc = make_float4(f0.x, f0.y, f1.x, f1.y);
        } else {
            acc.x += f0.x; acc.y += f0.y; acc.z += f1.x; acc.w += f1.y;
        }
    }
}

__global__ void __launch_bounds__(256) agg_kernel() {
    __shared__ uint2 buf[8][3][PF * 32];   // 8 warps x 3 stages x 2KB = 48KB
    int wid = threadIdx.x >> 5, lane = threadIdx.x & 31;
    int wrp = blockIdx.x * 8 + wid;
    if (wrp >= NWRP) return;
    const int base = wrp * CHUNK;

    uint2* sp[3] = { buf[wid][0], buf[wid][1], buf[wid][2] };
    int2 qs[3];
    float4 acc = make_float4(0, 0, 0, 0);
    int cur = -1;

    issue_batch(base,            lane, sp[0], qs[0]);
    issue_batch(base + PF,       lane, sp[1], qs[1]);

#pragma unroll
    for (int b = 0; b < NB; b++) {
        if (b < NB - 2) {
            issue_batch(base + (b + 2) * PF, lane, sp[(b + 2) % 3], qs[(b + 2) % 3]);
            CP_WAIT(2);
        } else if (b == NB - 2) {
            CP_WAIT(1);
        } else {
            CP_WAIT(0);
        }
        consume_batch(lane, sp[b % 3], qs[b % 3], acc, cur);
    }
    if (cur >= 0) atomicAdd(&((float4*)g_h)[cur * 32 + lane], acc);
}

// ---------------------------------------------------------------------------
// GEMM via fma.rn.f32x2, even/odd-k packed accumulators (unchanged).
// ---------------------------------------------------------------------------
#define WT_PITCH 132
#define WT_FLOATS (128 * WT_PITCH)
#define XS_OFF_B  (WT_FLOATS * 4)
#define GEMM_SMEM (XS_OFF_B + 64 * 128 * 4)

__device__ __forceinline__ float2 unpk(unsigned long long v) {
    float2 r;
    asm("mov.b64 {%0, %1}, %2;" : "=f"(r.x), "=f"(r.y) : "l"(v));
    return r;
}

template <int PASS>
__global__ __launch_bounds__(128)
void gemm_kernel(const float* __restrict__ Wg,
                 const float* __restrict__ bias,
                 float*       __restrict__ outp,
                 const float* __restrict__ gamma,
                 const float* __restrict__ beta) {
    extern __shared__ float sh[];
    __shared__ __align__(16) float ssum[128];
    __shared__ __align__(16) float ssq[128];
    __shared__ __align__(16) float sa[128];
    __shared__ __align__(16) float sb[128];

    const int t    = threadIdx.x;
    const int lane = t & 31;
    const int wrp  = t >> 5;

    if (PASS == 1) { ssum[t] = 0.f; ssq[t] = 0.f; }
    if (PASS == 2) {
        const float inv = 1.0f / (float)NN;
        float mean = g_sum[t] * inv;
        float var  = g_sumsq[t] * inv - mean * mean;
        float s = gamma[t] * rsqrtf(var + 1e-5f);
        sa[t] = s;
        sb[t] = beta[t] - mean * s;
    }
    __syncthreads();

    // Stage W transposed: Wt[c][k] = W[k][c], pitch 132
    {
        const int c = t;
        for (int g = 0; g < 32; g++) {
            int k0 = g * 4;
            float w0 = Wg[(k0 + 0) * 128 + c];
            float w1 = Wg[(k0 + 1) * 128 + c];
            float w2 = Wg[(k0 + 2) * 128 + c];
            float w3 = Wg[(k0 + 3) * 128 + c];
            *(float4*)&sh[c * WT_PITCH + k0] = make_float4(w0, w1, w2, w3);
        }
    }

    const float4* in4 = (PASS == 1) ? (const float4*)g_h : (const float4*)g_h1;
    float* xs = sh + WT_FLOATS;
    const int rowbase = blockIdx.x * 64;
#pragma unroll
    for (int j = 0; j < 16; j++) {
        int p = t + j * 128;
        int row = p >> 5, cp = p & 31;
        int gr = rowbase + row;
        float4 v = make_float4(0, 0, 0, 0);
        if (gr < NN) v = in4[gr * 32 + cp];
        if (PASS == 2) {
            float4 a = *(const float4*)&sa[cp * 4];
            float4 b = *(const float4*)&sb[cp * 4];
            v.x = fmaxf(fmaf(v.x, a.x, b.x), 0.f);
            v.y = fmaxf(fmaf(v.y, a.y, b.y), 0.f);
            v.z = fmaxf(fmaf(v.z, a.z, b.z), 0.f);
            v.w = fmaxf(fmaf(v.w, a.w, b.w), 0.f);
        }
        *(float4*)&xs[row * 128 + cp * 4] = v;
    }
    __syncthreads();

    float* out_f = (PASS == 1) ? (float*)g_h1 : outp;

    float bv[4];
#pragma unroll
    for (int cc = 0; cc < 4; cc++) bv[cc] = bias[lane + 32 * cc];

    const unsigned shb = (unsigned)__cvta_generic_to_shared(sh);
    unsigned wb[4];
#pragma unroll
    for (int cc = 0; cc < 4; cc++) wb[cc] = shb + (unsigned)((lane + 32 * cc) * WT_PITCH) * 4u;
    const unsigned xsb = shb + XS_OFF_B;

    float ts[4] = {0, 0, 0, 0};
    float tq[4] = {0, 0, 0, 0};

    for (int half = 0; half < 2; half++) {
        const int r0 = half * 32 + wrp * 8;
        unsigned xr[8];
#pragma unroll
        for (int r = 0; r < 8; r++) xr[r] = xsb + (unsigned)((r0 + r) * 128) * 4u;

        unsigned long long acc[8][4];
#pragma unroll
        for (int r = 0; r < 8; r++)
#pragma unroll
            for (int cc = 0; cc < 4; cc++) acc[r][cc] = 0ULL;

#pragma unroll 4
        for (int k = 0; k < 128; k += 4) {
            unsigned long long w01[4], w23[4];
#pragma unroll
            for (int cc = 0; cc < 4; cc++)
                asm("ld.shared.v2.b64 {%0, %1}, [%2];"
                    : "=l"(w01[cc]), "=l"(w23[cc]) : "r"(wb[cc] + (unsigned)(k * 4)));
#pragma unroll
            for (int r = 0; r < 8; r++) {
                unsigned long long x01, x23;
                asm("ld.shared.v2.b64 {%0, %1}, [%2];"
                    : "=l"(x01), "=l"(x23) : "r"(xr[r] + (unsigned)(k * 4)));
#pragma unroll
                for (int cc = 0; cc < 4; cc++) {
                    asm("fma.rn.f32x2 %0, %1, %2, %0;" : "+l"(acc[r][cc]) : "l"(x01), "l"(w01[cc]));
                    asm("fma.rn.f32x2 %0, %1, %2, %0;" : "+l"(acc[r][cc]) : "l"(x23), "l"(w23[cc]));
                }
            }
        }

#pragma unroll
        for (int r = 0; r < 8; r++) {
            int gr = rowbase + r0 + r;
            if (gr < NN) {
#pragma unroll
                for (int cc = 0; cc < 4; cc++) {
                    float2 p = unpk(acc[r][cc]);
                    float o = p.x + p.y + bv[cc];
                    out_f[gr * 128 + lane + 32 * cc] = o;
                    if (PASS == 1) { ts[cc] += o; tq[cc] += o * o; }
                }
            }
        }
    }

    if (PASS == 1) {
#pragma unroll
        for (int cc = 0; cc < 4; cc++) {
            atomicAdd(&ssum[lane + 32 * cc], ts[cc]);
            atomicAdd(&ssq [lane + 32 * cc], tq[cc]);
        }
        __syncthreads();
        atomicAdd(&g_sum[t],   ssum[t]);
        atomicAdd(&g_sumsq[t], ssq[t]);
    }
}

// ---------------------------------------------------------------------------
extern "C" void kernel_launch(void* const* d_in, const int* in_sizes, int n_in,
                              void* d_out, int out_size) {
    const float* x     = (const float*)d_in[0];
    const int*   ea    = (const int*)  d_in[1];
    const int*   src   = (const int*)  d_in[2];
    const int*   dst   = (const int*)  d_in[3];
    const float* bond  = (const float*)d_in[4];
    const float* eps   = (const float*)d_in[5];
    const float* W1    = (const float*)d_in[6];
    const float* b1    = (const float*)d_in[7];
    const float* gamma = (const float*)d_in[8];
    const float* beta  = (const float*)d_in[9];
    const float* W2    = (const float*)d_in[10];
    const float* b2    = (const float*)d_in[11];

    cudaFuncSetAttribute(gemm_kernel<1>, cudaFuncAttributeMaxDynamicSharedMemorySize, GEMM_SMEM);
    cudaFuncSetAttribute(gemm_kernel<2>, cudaFuncAttributeMaxDynamicSharedMemorySize, GEMM_SMEM);

    fused_setup<<<(NN * 32 + 255) / 256, 256>>>((const float4*)x, bond, dst, eps);
    scan_kernel<<<NBLK, SCAN_B>>>();
    scatter_kernel<<<(EE + 255) / 256, 256>>>(src, dst, ea);
    agg_kernel<<<(NWRP + 7) / 8, 256>>>();
    gemm_kernel<1><<<(NN + 63) / 64, 128, GEMM_SMEM>>>(W1, b1, nullptr, nullptr, nullptr);
    gemm_kernel<2><<<(NN + 63) / 64, 128, GEMM_SMEM>>>(W2, b2, (float*)d_out, gamma, beta);
}

// round 14
// speedup vs baseline: 1.2041x; 1.0127x over previous
#include <cuda_runtime.h>
#include <cuda_fp16.h>

#define NN 50000
#define EE 1600000
#define SCAN_B 256
#define NBLK ((NN + SCAN_B - 1) / SCAN_B)   // 196
#define CHUNK 128                            // edges per warp in agg
#define PF 8                                 // edges per pipeline batch
#define NB (CHUNK / PF)                      // 16 batches
#define NWRP (EE / CHUNK)                    // 12500 (exact)

// Scratch (device globals; zero-initialized at module load)
__device__ __align__(16) float4 g_h [NN * 32];     // (1+eps)x preload, RED-accumulated
__device__ __align__(16) float4 g_h1[NN * 32];     // h @ W1 + b1
__device__ float g_sum[128];
__device__ float g_sumsq[128];
__device__ __align__(16) __half g_ch[125 * 128];   // combo table fp16 (32KB, L1-hot)
__device__ __align__(16) uint2 g_xh[NN * 32];      // x in fp16
__device__ int  g_deg[NN];                         // zeroed by scan_kernel after use
__device__ int  g_off[NN];
__device__ int  g_cur[NN];
__device__ int  g_bsum[NBLK];
__device__ int  g_boff[NBLK];
__device__ int  g_scan_done;                       // reset by fused_setup each call
__device__ volatile int g_ready;                   // reset by fused_setup each call
__device__ __align__(16) int2 g_csr2[EE];          // {src<<7|code, dst} grouped by dst

// ---------------------------------------------------------------------------
// Fused setup: x->fp16, g_h=(1+eps)x, combo table, dst histogram, flag reset.
// ---------------------------------------------------------------------------
__global__ void fused_setup(const float4* __restrict__ x4,
                            const float*  __restrict__ be,
                            const int*    __restrict__ dst,
                            const float*  __restrict__ eps) {
    int i = blockIdx.x * blockDim.x + threadIdx.x;
    if (i == 0) { g_scan_done = 0; g_ready = 0; }
    if (i < NN * 32) {
        float4 v = x4[i];
        __half2 lo = __float22half2_rn(make_float2(v.x, v.y));
        __half2 hi = __float22half2_rn(make_float2(v.z, v.w));
        uint2 p;
        p.x = *(unsigned*)&lo;
        p.y = *(unsigned*)&hi;
        g_xh[i] = p;
        float c = 1.0f + *eps;
        g_h[i] = make_float4(c * v.x, c * v.y, c * v.z, c * v.w);
    }
    if (i < 125 * 128) {
        int c = i >> 7, t = i & 127;
        float s = be[(c / 25) * 128 + t]
                + be[(5 + (c / 5) % 5) * 128 + t]
                + be[(10 + c % 5) * 128 + t];
        g_ch[i] = __float2half_rn(s);
    }
    if (i < EE) atomicAdd(&g_deg[dst[i]], 1);
}

// ---------------------------------------------------------------------------
// Single-pass chip-wide exclusive scan of g_deg -> g_off / g_cur; zeroes
// g_deg for the next call and the BN stat accumulators (block 0).
// ---------------------------------------------------------------------------
__global__ void scan_kernel() {
    __shared__ int ws[8];
    __shared__ int sh2[SCAN_B];
    __shared__ bool is_last;
    int t = threadIdx.x, lane = t & 31, w = t >> 5, b = blockIdx.x;

    if (b == 0 && t < 128) { g_sum[t] = 0.f; g_sumsq[t] = 0.f; }

    int i = b * SCAN_B + t;
    int v = (i < NN) ? g_deg[i] : 0;
    if (i < NN) g_deg[i] = 0;          // reset for next kernel_launch call

    int s = v;
#pragma unroll
    for (int o = 1; o < 32; o <<= 1) {
        int u = __shfl_up_sync(0xffffffffu, s, o);
        if (lane >= o) s += u;
    }
    if (lane == 31) ws[w] = s;
    __syncthreads();
    if (t < 8) {
        int a = ws[t];
#pragma unroll
        for (int o = 1; o < 8; o <<= 1) {
            int u = __shfl_up_sync(0xffu, a, o);
            if (t >= o) a += u;
        }
        ws[t] = a;
    }
    __syncthreads();

    if (t == 0) {
        g_bsum[b] = ws[7];
        __threadfence();
        int done = atomicAdd(&g_scan_done, 1);
        is_last = (done == NBLK - 1);
    }
    __syncthreads();

    if (is_last) {
        int val = (t < NBLK) ? g_bsum[t] : 0;
        sh2[t] = val;
        __syncthreads();
        for (int o = 1; o < SCAN_B; o <<= 1) {
            int u = (t >= o) ? sh2[t - o] : 0;
            __syncthreads();
            sh2[t] += u;
            __syncthreads();
        }
        if (t < NBLK) g_boff[t] = sh2[t] - val;
        __threadfence();
        __syncthreads();
        if (t == 0) g_ready = 1;
    }

    if (t == 0) { while (g_ready == 0) { } }
    __syncthreads();
    __threadfence();

    int ex = s - v + (w ? ws[w - 1] : 0) + g_boff[b];
    if (i < NN) { g_off[i] = ex; g_cur[i] = ex; }
}

__global__ void scatter_kernel(const int* __restrict__ src,
                               const int* __restrict__ dst,
                               const int* __restrict__ ea) {
    int e = blockIdx.x * blockDim.x + threadIdx.x;
    if (e >= EE) return;
    int d = dst[e];
    int code = (ea[e * 3 + 0] * 5 + ea[e * 3 + 1]) * 5 + ea[e * 3 + 2];
    int pos = atomicAdd(&g_cur[d], 1);
    g_csr2[pos] = make_int2((src[e] << 7) | code, d);
}

// ---------------------------------------------------------------------------
// Aggregation: one warp per 128-edge CSR chunk. TWO-stage cp.async pipeline
// (32KB/block -> ~6-7 co-resident blocks, high occupancy); combo loads hit
// L1; dst-boundary flush via float4 atomicAdd (CSR is dst-sorted).
// ---------------------------------------------------------------------------
#define CP_ASYNC8(sa, ga) \
    asm volatile("cp.async.ca.shared.global [%0], [%1], 8;" :: "r"(sa), "l"(ga))
#define CP_COMMIT() asm volatile("cp.async.commit_group;" ::: "memory")
#define CP_WAIT(n)  asm volatile("cp.async.wait_group " #n ";" ::: "memory")

__device__ __forceinline__ void issue_batch(int ebase, int lane, uint2* sbuf, int2& qn) {
    qn = g_csr2[ebase + (lane & 7)];
#pragma unroll
    for (int j = 0; j < PF; j++) {
        int sx = __shfl_sync(0xffffffffu, qn.x, j) >> 7;
        unsigned sa = (unsigned)__cvta_generic_to_shared(&sbuf[j * 32 + lane]);
        CP_ASYNC8(sa, &g_xh[sx * 32 + lane]);
    }
    CP_COMMIT();
}

__device__ __forceinline__ void consume_batch(int lane, const uint2* sbuf, int2 qc,
                                              float4& acc, int& cur) {
    const uint2* ch2 = (const uint2*)g_ch;
    const __half2 z = __float2half2_rn(0.f);
#pragma unroll
    for (int j = 0; j < PF; j++) {
        int wv = __shfl_sync(0xffffffffu, qc.x, j);
        int d  = __shfl_sync(0xffffffffu, qc.y, j);
        uint2 xv = sbuf[j * 32 + lane];
        uint2 cv = ch2[(wv & 127) * 32 + lane];
        __half2 m0 = __hmax2(__hadd2(*(__half2*)&xv.x, *(__half2*)&cv.x), z);
        __half2 m1 = __hmax2(__hadd2(*(__half2*)&xv.y, *(__half2*)&cv.y), z);
        float2 f0 = __half22float2(m0);
        float2 f1 = __half22float2(m1);
        if (d != cur) {
            if (cur >= 0) atomicAdd(&((float4*)g_h)[cur * 32 + lane], acc);
            cur = d;
            acc = make_float4(f0.x, f0.y, f1.x, f1.y);
        } else {
            acc.x += f0.x; acc.y += f0.y; acc.z += f1.x; acc.w += f1.y;
        }
    }
}

__global__ void __launch_bounds__(256) agg_kernel() {
    __shared__ uint2 buf[8][2][PF * 32];   // 8 warps x 2 stages x 2KB = 32KB
    int wid = threadIdx.x >> 5, lane = threadIdx.x & 31;
    int wrp = blockIdx.x * 8 + wid;
    if (wrp >= NWRP) return;
    const int base = wrp * CHUNK;

    uint2* sp[2] = { buf[wid][0], buf[wid][1] };
    int2 qs[2];
    float4 acc = make_float4(0, 0, 0, 0);
    int cur = -1;

    issue_batch(base, lane, sp[0], qs[0]);

#pragma unroll
    for (int b = 0; b < NB; b++) {
        if (b < NB - 1) {
            issue_batch(base + (b + 1) * PF, lane, sp[(b + 1) & 1], qs[(b + 1) & 1]);
            CP_WAIT(1);
        } else {
            CP_WAIT(0);
        }
        consume_batch(lane, sp[b & 1], qs[b & 1], acc, cur);
    }
    if (cur >= 0) atomicAdd(&((float4*)g_h)[cur * 32 + lane], acc);
}

// ---------------------------------------------------------------------------
// GEMM via fma.rn.f32x2, even/odd-k packed accumulators (unchanged).
// ---------------------------------------------------------------------------
#define WT_PITCH 132
#define WT_FLOATS (128 * WT_PITCH)
#define XS_OFF_B  (WT_FLOATS * 4)
#define GEMM_SMEM (XS_OFF_B + 64 * 128 * 4)

__device__ __forceinline__ float2 unpk(unsigned long long v) {
    float2 r;
    asm("mov.b64 {%0, %1}, %2;" : "=f"(r.x), "=f"(r.y) : "l"(v));
    return r;
}

template <int PASS>
__global__ __launch_bounds__(128)
void gemm_kernel(const float* __restrict__ Wg,
                 const float* __restrict__ bias,
                 float*       __restrict__ outp,
                 const float* __restrict__ gamma,
                 const float* __restrict__ beta) {
    extern __shared__ float sh[];
    __shared__ __align__(16) float ssum[128];
    __shared__ __align__(16) float ssq[128];
    __shared__ __align__(16) float sa[128];
    __shared__ __align__(16) float sb[128];

    const int t    = threadIdx.x;
    const int lane = t & 31;
    const int wrp  = t >> 5;

    if (PASS == 1) { ssum[t] = 0.f; ssq[t] = 0.f; }
    if (PASS == 2) {
        const float inv = 1.0f / (float)NN;
        float mean = g_sum[t] * inv;
        float var  = g_sumsq[t] * inv - mean * mean;
        float s = gamma[t] * rsqrtf(var + 1e-5f);
        sa[t] = s;
        sb[t] = beta[t] - mean * s;
    }
    __syncthreads();

    // Stage W transposed: Wt[c][k] = W[k][c], pitch 132
    {
        const int c = t;
        for (int g = 0; g < 32; g++) {
            int k0 = g * 4;
            float w0 = Wg[(k0 + 0) * 128 + c];
            float w1 = Wg[(k0 + 1) * 128 + c];
            float w2 = Wg[(k0 + 2) * 128 + c];
            float w3 = Wg[(k0 + 3) * 128 + c];
            *(float4*)&sh[c * WT_PITCH + k0] = make_float4(w0, w1, w2, w3);
        }
    }

    const float4* in4 = (PASS == 1) ? (const float4*)g_h : (const float4*)g_h1;
    float* xs = sh + WT_FLOATS;
    const int rowbase = blockIdx.x * 64;
#pragma unroll
    for (int j = 0; j < 16; j++) {
        int p = t + j * 128;
        int row = p >> 5, cp = p & 31;
        int gr = rowbase + row;
        float4 v = make_float4(0, 0, 0, 0);
        if (gr < NN) v = in4[gr * 32 + cp];
        if (PASS == 2) {
            float4 a = *(const float4*)&sa[cp * 4];
            float4 b = *(const float4*)&sb[cp * 4];
            v.x = fmaxf(fmaf(v.x, a.x, b.x), 0.f);
            v.y = fmaxf(fmaf(v.y, a.y, b.y), 0.f);
            v.z = fmaxf(fmaf(v.z, a.z, b.z), 0.f);
            v.w = fmaxf(fmaf(v.w, a.w, b.w), 0.f);
        }
        *(float4*)&xs[row * 128 + cp * 4] = v;
    }
    __syncthreads();

    float* out_f = (PASS == 1) ? (float*)g_h1 : outp;

    float bv[4];
#pragma unroll
    for (int cc = 0; cc < 4; cc++) bv[cc] = bias[lane + 32 * cc];

    const unsigned shb = (unsigned)__cvta_generic_to_shared(sh);
    unsigned wb[4];
#pragma unroll
    for (int cc = 0; cc < 4; cc++) wb[cc] = shb + (unsigned)((lane + 32 * cc) * WT_PITCH) * 4u;
    const unsigned xsb = shb + XS_OFF_B;

    float ts[4] = {0, 0, 0, 0};
    float tq[4] = {0, 0, 0, 0};

    for (int half = 0; half < 2; half++) {
        const int r0 = half * 32 + wrp * 8;
        unsigned xr[8];
#pragma unroll
        for (int r = 0; r < 8; r++) xr[r] = xsb + (unsigned)((r0 + r) * 128) * 4u;

        unsigned long long acc[8][4];
#pragma unroll
        for (int r = 0; r < 8; r++)
#pragma unroll
            for (int cc = 0; cc < 4; cc++) acc[r][cc] = 0ULL;

#pragma unroll 4
        for (int k = 0; k < 128; k += 4) {
            unsigned long long w01[4], w23[4];
#pragma unroll
            for (int cc = 0; cc < 4; cc++)
                asm("ld.shared.v2.b64 {%0, %1}, [%2];"
                    : "=l"(w01[cc]), "=l"(w23[cc]) : "r"(wb[cc] + (unsigned)(k * 4)));
#pragma unroll
            for (int r = 0; r < 8; r++) {
                unsigned long long x01, x23;
                asm("ld.shared.v2.b64 {%0, %1}, [%2];"
                    : "=l"(x01), "=l"(x23) : "r"(xr[r] + (unsigned)(k * 4)));
#pragma unroll
                for (int cc = 0; cc < 4; cc++) {
                    asm("fma.rn.f32x2 %0, %1, %2, %0;" : "+l"(acc[r][cc]) : "l"(x01), "l"(w01[cc]));
                    asm("fma.rn.f32x2 %0, %1, %2, %0;" : "+l"(acc[r][cc]) : "l"(x23), "l"(w23[cc]));
                }
            }
        }

#pragma unroll
        for (int r = 0; r < 8; r++) {
            int gr = rowbase + r0 + r;
            if (gr < NN) {
#pragma unroll
                for (int cc = 0; cc < 4; cc++) {
                    float2 p = unpk(acc[r][cc]);
                    float o = p.x + p.y + bv[cc];
                    out_f[gr * 128 + lane + 32 * cc] = o;
                    if (PASS == 1) { ts[cc] += o; tq[cc] += o * o; }
                }
            }
        }
    }

    if (PASS == 1) {
#pragma unroll
        for (int cc = 0; cc < 4; cc++) {
            atomicAdd(&ssum[lane + 32 * cc], ts[cc]);
            atomicAdd(&ssq [lane + 32 * cc], tq[cc]);
        }
        __syncthreads();
        atomicAdd(&g_sum[t],   ssum[t]);
        atomicAdd(&g_sumsq[t], ssq[t]);
    }
}

// ---------------------------------------------------------------------------
extern "C" void kernel_launch(void* const* d_in, const int* in_sizes, int n_in,
                              void* d_out, int out_size) {
    const float* x     = (const float*)d_in[0];
    const int*   ea    = (const int*)  d_in[1];
    const int*   src   = (const int*)  d_in[2];
    const int*   dst   = (const int*)  d_in[3];
    const float* bond  = (const float*)d_in[4];
    const float* eps   = (const float*)d_in[5];
    const float* W1    = (const float*)d_in[6];
    const float* b1    = (const float*)d_in[7];
    const float* gamma = (const float*)d_in[8];
    const float* beta  = (const float*)d_in[9];
    const float* W2    = (const float*)d_in[10];
    const float* b2    = (const float*)d_in[11];

    cudaFuncSetAttribute(gemm_kernel<1>, cudaFuncAttributeMaxDynamicSharedMemorySize, GEMM_SMEM);
    cudaFuncSetAttribute(gemm_kernel<2>, cudaFuncAttributeMaxDynamicSharedMemorySize, GEMM_SMEM);

    fused_setup<<<(NN * 32 + 255) / 256, 256>>>((const float4*)x, bond, dst, eps);
    scan_kernel<<<NBLK, SCAN_B>>>();
    scatter_kernel<<<(EE + 255) / 256, 256>>>(src, dst, ea);
    agg_kernel<<<(NWRP + 7) / 8, 256>>>();
    gemm_kernel<1><<<(NN + 63) / 64, 128, GEMM_SMEM>>>(W1, b1, nullptr, nullptr, nullptr);
    gemm_kernel<2><<<(NN + 63) / 64, 128, GEMM_SMEM>>>(W2, b2, (float*)d_out, gamma, beta);
}

// round 15
// speedup vs baseline: 1.2766x; 1.0602x over previous
#include <cuda_runtime.h>
#include <cuda_fp16.h>

#define NN 50000
#define EE 1600000
#define SCAN_B 256
#define NBLK ((NN + SCAN_B - 1) / SCAN_B)   // 196
#define CHUNK 128
#define PF 8
#define NB (CHUNK / PF)
#define NWRP (EE / CHUNK)                    // 12500

// Scratch (device globals; zero-initialized at module load)
__device__ __align__(16) float4 g_h [NN * 32];
__device__ __align__(16) float4 g_h1[NN * 32];
__device__ float g_sum[128];
__device__ float g_sumsq[128];
__device__ __align__(16) __half g_ch[125 * 128];
__device__ __align__(16) uint2 g_xh[NN * 32];
__device__ int  g_deg[NN];
__device__ int  g_off[NN];
__device__ int  g_cur[NN];
__device__ int  g_bsum[NBLK];
__device__ int  g_boff[NBLK];
__device__ int  g_scan_done;
__device__ volatile int g_ready;
__device__ __align__(16) int2 g_csr2[EE];

// ---------------------------------------------------------------------------
__global__ void fused_setup(const float4* __restrict__ x4,
                            const float*  __restrict__ be,
                            const int*    __restrict__ dst,
                            const float*  __restrict__ eps) {
    int i = blockIdx.x * blockDim.x + threadIdx.x;
    if (i == 0) { g_scan_done = 0; g_ready = 0; }
    if (i < NN * 32) {
        float4 v = x4[i];
        __half2 lo = __float22half2_rn(make_float2(v.x, v.y));
        __half2 hi = __float22half2_rn(make_float2(v.z, v.w));
        uint2 p;
        p.x = *(unsigned*)&lo;
        p.y = *(unsigned*)&hi;
        g_xh[i] = p;
        float c = 1.0f + *eps;
        g_h[i] = make_float4(c * v.x, c * v.y, c * v.z, c * v.w);
    }
    if (i < 125 * 128) {
        int c = i >> 7, t = i & 127;
        float s = be[(c / 25) * 128 + t]
                + be[(5 + (c / 5) % 5) * 128 + t]
                + be[(10 + c % 5) * 128 + t];
        g_ch[i] = __float2half_rn(s);
    }
    if (i < EE) atomicAdd(&g_deg[dst[i]], 1);
}

// ---------------------------------------------------------------------------
__global__ void scan_kernel() {
    __shared__ int ws[8];
    __shared__ int sh2[SCAN_B];
    __shared__ bool is_last;
    int t = threadIdx.x, lane = t & 31, w = t >> 5, b = blockIdx.x;

    if (b == 0 && t < 128) { g_sum[t] = 0.f; g_sumsq[t] = 0.f; }

    int i = b * SCAN_B + t;
    int v = (i < NN) ? g_deg[i] : 0;
    if (i < NN) g_deg[i] = 0;

    int s = v;
#pragma unroll
    for (int o = 1; o < 32; o <<= 1) {
        int u = __shfl_up_sync(0xffffffffu, s, o);
        if (lane >= o) s += u;
    }
    if (lane == 31) ws[w] = s;
    __syncthreads();
    if (t < 8) {
        int a = ws[t];
#pragma unroll
        for (int o = 1; o < 8; o <<= 1) {
            int u = __shfl_up_sync(0xffu, a, o);
            if (t >= o) a += u;
        }
        ws[t] = a;
    }
    __syncthreads();

    if (t == 0) {
        g_bsum[b] = ws[7];
        __threadfence();
        int done = atomicAdd(&g_scan_done, 1);
        is_last = (done == NBLK - 1);
    }
    __syncthreads();

    if (is_last) {
        int val = (t < NBLK) ? g_bsum[t] : 0;
        sh2[t] = val;
        __syncthreads();
        for (int o = 1; o < SCAN_B; o <<= 1) {
            int u = (t >= o) ? sh2[t - o] : 0;
            __syncthreads();
            sh2[t] += u;
            __syncthreads();
        }
        if (t < NBLK) g_boff[t] = sh2[t] - val;
        __threadfence();
        __syncthreads();
        if (t == 0) g_ready = 1;
    }

    if (t == 0) { while (g_ready == 0) { } }
    __syncthreads();
    __threadfence();

    int ex = s - v + (w ? ws[w - 1] : 0) + g_boff[b];
    if (i < NN) { g_off[i] = ex; g_cur[i] = ex; }
}

__global__ void scatter_kernel(const int* __restrict__ src,
                               const int* __restrict__ dst,
                               const int* __restrict__ ea) {
    int e = blockIdx.x * blockDim.x + threadIdx.x;
    if (e >= EE) return;
    int d = dst[e];
    int code = (ea[e * 3 + 0] * 5 + ea[e * 3 + 1]) * 5 + ea[e * 3 + 2];
    int pos = atomicAdd(&g_cur[d], 1);
    g_csr2[pos] = make_int2((src[e] << 7) | code, d);
}

// ---------------------------------------------------------------------------
// Aggregation (unchanged from R14): warp per 128-edge chunk, 2-stage cp.async.
// ---------------------------------------------------------------------------
#define CP_ASYNC8(sa, ga) \
    asm volatile("cp.async.ca.shared.global [%0], [%1], 8;" :: "r"(sa), "l"(ga))
#define CP_COMMIT() asm volatile("cp.async.commit_group;" ::: "memory")
#define CP_WAIT(n)  asm volatile("cp.async.wait_group " #n ";" ::: "memory")

__device__ __forceinline__ void issue_batch(int ebase, int lane, uint2* sbuf, int2& qn) {
    qn = g_csr2[ebase + (lane & 7)];
#pragma unroll
    for (int j = 0; j < PF; j++) {
        int sx = __shfl_sync(0xffffffffu, qn.x, j) >> 7;
        unsigned sa = (unsigned)__cvta_generic_to_shared(&sbuf[j * 32 + lane]);
        CP_ASYNC8(sa, &g_xh[sx * 32 + lane]);
    }
    CP_COMMIT();
}

__device__ __forceinline__ void consume_batch(int lane, const uint2* sbuf, int2 qc,
                                              float4& acc, int& cur) {
    const uint2* ch2 = (const uint2*)g_ch;
    const __half2 z = __float2half2_rn(0.f);
#pragma unroll
    for (int j = 0; j < PF; j++) {
        int wv = __shfl_sync(0xffffffffu, qc.x, j);
        int d  = __shfl_sync(0xffffffffu, qc.y, j);
        uint2 xv = sbuf[j * 32 + lane];
        uint2 cv = ch2[(wv & 127) * 32 + lane];
        __half2 m0 = __hmax2(__hadd2(*(__half2*)&xv.x, *(__half2*)&cv.x), z);
        __half2 m1 = __hmax2(__hadd2(*(__half2*)&xv.y, *(__half2*)&cv.y), z);
        float2 f0 = __half22float2(m0);
        float2 f1 = __half22float2(m1);
        if (d != cur) {
            if (cur >= 0) atomicAdd(&((float4*)g_h)[cur * 32 + lane], acc);
            cur = d;
            acc = make_float4(f0.x, f0.y, f1.x, f1.y);
        } else {
            acc.x += f0.x; acc.y += f0.y; acc.z += f1.x; acc.w += f1.y;
        }
    }
}

__global__ void __launch_bounds__(256) agg_kernel() {
    __shared__ uint2 buf[8][2][PF * 32];
    int wid = threadIdx.x >> 5, lane = threadIdx.x & 31;
    int wrp = blockIdx.x * 8 + wid;
    if (wrp >= NWRP) return;
    const int base = wrp * CHUNK;

    uint2* sp[2] = { buf[wid][0], buf[wid][1] };
    int2 qs[2];
    float4 acc = make_float4(0, 0, 0, 0);
    int cur = -1;

    issue_batch(base, lane, sp[0], qs[0]);
#pragma unroll
    for (int b = 0; b < NB; b++) {
        if (b < NB - 1) {
            issue_batch(base + (b + 1) * PF, lane, sp[(b + 1) & 1], qs[(b + 1) & 1]);
            CP_WAIT(1);
        } else {
            CP_WAIT(0);
        }
        consume_batch(lane, sp[b & 1], qs[b & 1], acc, cur);
    }
    if (cur >= 0) atomicAdd(&((float4*)g_h)[cur * 32 + lane], acc);
}

// ---------------------------------------------------------------------------
// GEMM1 via HMMA (mma.sync.m16n8k16, fp16 in / fp32 acc): h1 = h @ W1 + b1,
// with BN column sum/sumsq accumulation.
// smem: A = h tile [64][136] fp16 (pad 8 halves -> conflict-free ldmatrix),
//       Bt = W1^T [128 n][136 k] fp16. Block 128 thr; warp w -> rows w*16..+15.
// ---------------------------------------------------------------------------
#define AP 136                            // padded halves per row
#define APB (AP * 2)                      // 272 bytes per row
#define SH_A_BYTES (64 * APB)             // 17408
#define SH_BT_OFF  SH_A_BYTES
#define G1_SMEM (SH_A_BYTES + 128 * APB)  // 52224

#define LDSM_X4(r0, r1, r2, r3, a) \
    asm volatile("ldmatrix.sync.aligned.m8n8.x4.shared.b16 {%0,%1,%2,%3}, [%4];" \
                 : "=r"(r0), "=r"(r1), "=r"(r2), "=r"(r3) : "r"(a))
#define MMA16816(d0, d1, d2, d3, a0, a1, a2, a3, b0, b1) \
    asm volatile("mma.sync.aligned.m16n8k16.row.col.f32.f16.f16.f32 " \
                 "{%0,%1,%2,%3},{%4,%5,%6,%7},{%8,%9},{%0,%1,%2,%3};" \
                 : "+f"(d0), "+f"(d1), "+f"(d2), "+f"(d3) \
                 : "r"(a0), "r"(a1), "r"(a2), "r"(a3), "r"(b0), "r"(b1))

__global__ __launch_bounds__(128)
void gemm1_hmma(const float* __restrict__ Wg, const float* __restrict__ bias) {
    extern __shared__ char shm[];
    __shared__ float ssum[128], ssq[128], sbias[128];
    const int t = threadIdx.x, lane = t & 31, w = t >> 5;
    const int rowbase = blockIdx.x * 64;

    ssum[t] = 0.f; ssq[t] = 0.f; sbias[t] = bias[t];

    // Stage A: h rows (fp32 -> fp16), 64 x 128, pitch 136 halves
    {
        const float2* h2 = (const float2*)g_h;
#pragma unroll
        for (int j = 0; j < 32; j++) {
            int idx2 = t + j * 128;             // 4096 float2 total
            int row = idx2 >> 6, c2 = idx2 & 63;
            int gr = rowbase + row;
            float2 v = (gr < NN) ? h2[gr * 64 + c2] : make_float2(0.f, 0.f);
            *(__half2*)(shm + row * APB + c2 * 4) = __float22half2_rn(v);
        }
    }
    // Stage Bt: W^T [n][k] fp16, pitch 136 halves. Thread t owns n = t.
    {
        char* bt = shm + SH_BT_OFF;
#pragma unroll 8
        for (int k2 = 0; k2 < 64; k2++) {
            float w0 = Wg[(2 * k2) * 128 + t];
            float w1 = Wg[(2 * k2 + 1) * 128 + t];
            *(__half2*)(bt + t * APB + k2 * 4) = __float22half2_rn(make_float2(w0, w1));
        }
    }
    __syncthreads();

    const unsigned sa_base = (unsigned)__cvta_generic_to_shared(shm);
    const unsigned bt_base = sa_base + SH_BT_OFF;

    // A-frag address: group g=lane>>3: row=(g&1)*8+(lane&7), kof=(g>>1)*8
    const unsigned a_addr0 = sa_base + (unsigned)((w * 16 + ((lane >> 3) & 1) * 8 + (lane & 7)) * APB
                                                  + (((lane >> 4) & 1) * 8) * 2);
    // B-frag x4 (2 n-tiles): nrow = j*16 + (g>>1)*8 + (lane&7), kof=(g&1)*8
    const unsigned b_row_off = (unsigned)((((lane >> 4) & 1) * 8 + (lane & 7)) * APB);
    const unsigned b_k_off   = (unsigned)((((lane >> 3) & 1) * 8) * 2);

    float d[16][4];
#pragma unroll
    for (int nt = 0; nt < 16; nt++)
#pragma unroll
        for (int i = 0; i < 4; i++) d[nt][i] = 0.f;

#pragma unroll
    for (int ks = 0; ks < 8; ks++) {
        unsigned kb = (unsigned)(ks * 16 * 2);
        unsigned a0, a1, a2, a3;
        LDSM_X4(a0, a1, a2, a3, a_addr0 + kb);
#pragma unroll
        for (int j = 0; j < 8; j++) {
            unsigned r0, r1, r2, r3;
            unsigned baddr = bt_base + (unsigned)(j * 16 * APB) + b_row_off + b_k_off + kb;
            LDSM_X4(r0, r1, r2, r3, baddr);
            MMA16816(d[2 * j][0], d[2 * j][1], d[2 * j][2], d[2 * j][3],
                     a0, a1, a2, a3, r0, r1);
            MMA16816(d[2 * j + 1][0], d[2 * j + 1][1], d[2 * j + 1][2], d[2 * j + 1][3],
                     a0, a1, a2, a3, r2, r3);
        }
    }

    // Epilogue: bias, store, BN stats
    const int r_lo = rowbase + w * 16 + (lane >> 2);
    const int r_hi = r_lo + 8;
    bool v_lo = (r_lo < NN), v_hi = (r_hi < NN);
    float2* out2 = (float2*)g_h1;

#pragma unroll
    for (int nt = 0; nt < 16; nt++) {
        int col = nt * 8 + (lane & 3) * 2;
        float b0 = sbias[col], b1 = sbias[col + 1];
        float o0 = d[nt][0] + b0, o1 = d[nt][1] + b1;
        float o2 = d[nt][2] + b0, o3 = d[nt][3] + b1;
        if (v_lo) out2[(r_lo * 128 + col) >> 1] = make_float2(o0, o1);
        if (v_hi) out2[(r_hi * 128 + col) >> 1] = make_float2(o2, o3);
        float ts0 = (v_lo ? o0 : 0.f) + (v_hi ? o2 : 0.f);
        float ts1 = (v_lo ? o1 : 0.f) + (v_hi ? o3 : 0.f);
        float tq0 = (v_lo ? o0 * o0 : 0.f) + (v_hi ? o2 * o2 : 0.f);
        float tq1 = (v_lo ? o1 * o1 : 0.f) + (v_hi ? o3 * o3 : 0.f);
        // reduce over lanes {l, l+4, ..., l+28}
#pragma unroll
        for (int o = 16; o >= 4; o >>= 1) {
            ts0 += __shfl_down_sync(0xffffffffu, ts0, o);
            ts1 += __shfl_down_sync(0xffffffffu, ts1, o);
            tq0 += __shfl_down_sync(0xffffffffu, tq0, o);
            tq1 += __shfl_down_sync(0xffffffffu, tq1, o);
        }
        if (lane < 4) {
            atomicAdd(&ssum[col], ts0);
            atomicAdd(&ssum[col + 1], ts1);
            atomicAdd(&ssq[col], tq0);
            atomicAdd(&ssq[col + 1], tq1);
        }
    }
    __syncthreads();
    atomicAdd(&g_sum[t],   ssum[t]);
    atomicAdd(&g_sumsq[t], ssq[t]);
}

// ---------------------------------------------------------------------------
// GEMM2 via fma.rn.f32x2 (unchanged): out = relu(BN(h1)) @ W2 + b2.
// ---------------------------------------------------------------------------
#define WT_PITCH 132
#define WT_FLOATS (128 * WT_PITCH)
#define XS_OFF_B  (WT_FLOATS * 4)
#define GEMM_SMEM (XS_OFF_B + 64 * 128 * 4)

__device__ __forceinline__ float2 unpk(unsigned long long v) {
    float2 r;
    asm("mov.b64 {%0, %1}, %2;" : "=f"(r.x), "=f"(r.y) : "l"(v));
    return r;
}

__global__ __launch_bounds__(128)
void gemm2_kernel(const float* __restrict__ Wg,
                  const float* __restrict__ bias,
                  float*       __restrict__ outp,
                  const float* __restrict__ gamma,
                  const float* __restrict__ beta) {
    extern __shared__ float sh[];
    __shared__ __align__(16) float sa[128];
    __shared__ __align__(16) float sb[128];

    const int t    = threadIdx.x;
    const int lane = t & 31;
    const int wrp  = t >> 5;

    {
        const float inv = 1.0f / (float)NN;
        float mean = g_sum[t] * inv;
        float var  = g_sumsq[t] * inv - mean * mean;
        float s = gamma[t] * rsqrtf(var + 1e-5f);
        sa[t] = s;
        sb[t] = beta[t] - mean * s;
    }
    __syncthreads();

    {
        const int c = t;
        for (int g = 0; g < 32; g++) {
            int k0 = g * 4;
            float w0 = Wg[(k0 + 0) * 128 + c];
            float w1 = Wg[(k0 + 1) * 128 + c];
            float w2 = Wg[(k0 + 2) * 128 + c];
            float w3 = Wg[(k0 + 3) * 128 + c];
            *(float4*)&sh[c * WT_PITCH + k0] = make_float4(w0, w1, w2, w3);
        }
    }

    const float4* in4 = (const float4*)g_h1;
    float* xs = sh + WT_FLOATS;
    const int rowbase = blockIdx.x * 64;
#pragma unroll
    for (int j = 0; j < 16; j++) {
        int p = t + j * 128;
        int row = p >> 5, cp = p & 31;
        int gr = rowbase + row;
        float4 v = make_float4(0, 0, 0, 0);
        if (gr < NN) v = in4[gr * 32 + cp];
        float4 a = *(const float4*)&sa[cp * 4];
        float4 b = *(const float4*)&sb[cp * 4];
        v.x = fmaxf(fmaf(v.x, a.x, b.x), 0.f);
        v.y = fmaxf(fmaf(v.y, a.y, b.y), 0.f);
        v.z = fmaxf(fmaf(v.z, a.z, b.z), 0.f);
        v.w = fmaxf(fmaf(v.w, a.w, b.w), 0.f);
        *(float4*)&xs[row * 128 + cp * 4] = v;
    }
    __syncthreads();

    float bv[4];
#pragma unroll
    for (int cc = 0; cc < 4; cc++) bv[cc] = bias[lane + 32 * cc];

    const unsigned shb = (unsigned)__cvta_generic_to_shared(sh);
    unsigned wb[4];
#pragma unroll
    for (int cc = 0; cc < 4; cc++) wb[cc] = shb + (unsigned)((lane + 32 * cc) * WT_PITCH) * 4u;
    const unsigned xsb = shb + XS_OFF_B;

    for (int half = 0; half < 2; half++) {
        const int r0 = half * 32 + wrp * 8;
        unsigned xr[8];
#pragma unroll
        for (int r = 0; r < 8; r++) xr[r] = xsb + (unsigned)((r0 + r) * 128) * 4u;

        unsigned long long acc[8][4];
#pragma unroll
        for (int r = 0; r < 8; r++)
#pragma unroll
            for (int cc = 0; cc < 4; cc++) acc[r][cc] = 0ULL;

#pragma unroll 4
        for (int k = 0; k < 128; k += 4) {
            unsigned long long w01[4], w23[4];
#pragma unroll
            for (int cc = 0; cc < 4; cc++)
                asm("ld.shared.v2.b64 {%0, %1}, [%2];"
                    : "=l"(w01[cc]), "=l"(w23[cc]) : "r"(wb[cc] + (unsigned)(k * 4)));
#pragma unroll
            for (int r = 0; r < 8; r++) {
                unsigned long long x01, x23;
                asm("ld.shared.v2.b64 {%0, %1}, [%2];"
                    : "=l"(x01), "=l"(x23) : "r"(xr[r] + (unsigned)(k * 4)));
#pragma unroll
                for (int cc = 0; cc < 4; cc++) {
                    asm("fma.rn.f32x2 %0, %1, %2, %0;" : "+l"(acc[r][cc]) : "l"(x01), "l"(w01[cc]));
                    asm("fma.rn.f32x2 %0, %1, %2, %0;" : "+l"(acc[r][cc]) : "l"(x23), "l"(w23[cc]));
                }
            }
        }

#pragma unroll
        for (int r = 0; r < 8; r++) {
            int gr = rowbase + r0 + r;
            if (gr < NN) {
#pragma unroll
                for (int cc = 0; cc < 4; cc++) {
                    float2 p = unpk(acc[r][cc]);
                    outp[gr * 128 + lane + 32 * cc] = p.x + p.y + bv[cc];
                }
            }
        }
    }
}

// ---------------------------------------------------------------------------
extern "C" void kernel_launch(void* const* d_in, const int* in_sizes, int n_in,
                              void* d_out, int out_size) {
    const float* x     = (const float*)d_in[0];
    const int*   ea    = (const int*)  d_in[1];
    const int*   src   = (const int*)  d_in[2];
    const int*   dst   = (const int*)  d_in[3];
    const float* bond  = (const float*)d_in[4];
    const float* eps   = (const float*)d_in[5];
    const float* W1    = (const float*)d_in[6];
    const float* b1    = (const float*)d_in[7];
    const float* gamma = (const float*)d_in[8];
    const float* beta  = (const float*)d_in[9];
    const float* W2    = (const float*)d_in[10];
    const float* b2    = (const float*)d_in[11];

    cudaFuncSetAttribute(gemm1_hmma,  cudaFuncAttributeMaxDynamicSharedMemorySize, G1_SMEM);
    cudaFuncSetAttribute(gemm2_kernel, cudaFuncAttributeMaxDynamicSharedMemorySize, GEMM_SMEM);

    fused_setup<<<(NN * 32 + 255) / 256, 256>>>((const float4*)x, bond, dst, eps);
    scan_kernel<<<NBLK, SCAN_B>>>();
    scatter_kernel<<<(EE + 255) / 256, 256>>>(src, dst, ea);
    agg_kernel<<<(NWRP + 7) / 8, 256>>>();
    gemm1_hmma<<<(NN + 63) / 64, 128, G1_SMEM>>>(W1, b1);
    gemm2_kernel<<<(NN + 63) / 64, 128, GEMM_SMEM>>>(W2, b2, (float*)d_out, gamma, beta);
}

// round 17
// speedup vs baseline: 1.3150x; 1.0301x over previous
#include <cuda_runtime.h>
#include <cuda_fp16.h>

#define NN 50000
#define EE 1600000
#define SCAN_B 256
#define NBLK ((NN + SCAN_B - 1) / SCAN_B)   // 196
#define CHUNK 128
#define PF 8
#define NB (CHUNK / PF)
#define NWRP (EE / CHUNK)                    // 12500

// Scratch (device globals; zero-initialized at module load)
__device__ __align__(16) float4 g_h [NN * 32];
__device__ __align__(16) float4 g_h1[NN * 32];
__device__ float g_sum[128];
__device__ float g_sumsq[128];
__device__ __align__(16) __half g_ch[125 * 128];
__device__ __align__(16) uint2 g_xh[NN * 32];
__device__ int  g_deg[NN];
__device__ int  g_off[NN];
__device__ int  g_cur[NN];
__device__ int  g_bsum[NBLK];
__device__ int  g_boff[NBLK];
__device__ int  g_scan_done;
__device__ volatile int g_ready;
__device__ __align__(16) int2 g_csr2[EE];

// ---------------------------------------------------------------------------
__global__ void fused_setup(const float4* __restrict__ x4,
                            const float*  __restrict__ be,
                            const int*    __restrict__ dst,
                            const float*  __restrict__ eps) {
    int i = blockIdx.x * blockDim.x + threadIdx.x;
    if (i == 0) { g_scan_done = 0; g_ready = 0; }
    if (i < NN * 32) {
        float4 v = x4[i];
        __half2 lo = __float22half2_rn(make_float2(v.x, v.y));
        __half2 hi = __float22half2_rn(make_float2(v.z, v.w));
        uint2 p;
        p.x = *(unsigned*)&lo;
        p.y = *(unsigned*)&hi;
        g_xh[i] = p;
        float c = 1.0f + *eps;
        g_h[i] = make_float4(c * v.x, c * v.y, c * v.z, c * v.w);
    }
    if (i < 125 * 128) {
        int c = i >> 7, t = i & 127;
        float s = be[(c / 25) * 128 + t]
                + be[(5 + (c / 5) % 5) * 128 + t]
                + be[(10 + c % 5) * 128 + t];
        g_ch[i] = __float2half_rn(s);
    }
    if (i < EE) atomicAdd(&g_deg[dst[i]], 1);
}

// ---------------------------------------------------------------------------
__global__ void scan_kernel() {
    __shared__ int ws[8];
    __shared__ int sh2[SCAN_B];
    __shared__ bool is_last;
    int t = threadIdx.x, lane = t & 31, w = t >> 5, b = blockIdx.x;

    if (b == 0 && t < 128) { g_sum[t] = 0.f; g_sumsq[t] = 0.f; }

    int i = b * SCAN_B + t;
    int v = (i < NN) ? g_deg[i] : 0;
    if (i < NN) g_deg[i] = 0;

    int s = v;
#pragma unroll
    for (int o = 1; o < 32; o <<= 1) {
        int u = __shfl_up_sync(0xffffffffu, s, o);
        if (lane >= o) s += u;
    }
    if (lane == 31) ws[w] = s;
    __syncthreads();
    if (t < 8) {
        int a = ws[t];
#pragma unroll
        for (int o = 1; o < 8; o <<= 1) {
            int u = __shfl_up_sync(0xffu, a, o);
            if (t >= o) a += u;
        }
        ws[t] = a;
    }
    __syncthreads();

    if (t == 0) {
        g_bsum[b] = ws[7];
        __threadfence();
        int done = atomicAdd(&g_scan_done, 1);
        is_last = (done == NBLK - 1);
    }
    __syncthreads();

    if (is_last) {
        int val = (t < NBLK) ? g_bsum[t] : 0;
        sh2[t] = val;
        __syncthreads();
        for (int o = 1; o < SCAN_B; o <<= 1) {
            int u = (t >= o) ? sh2[t - o] : 0;
            __syncthreads();
            sh2[t] += u;
            __syncthreads();
        }
        if (t < NBLK) g_boff[t] = sh2[t] - val;
        __threadfence();
        __syncthreads();
        if (t == 0) g_ready = 1;
    }

    if (t == 0) { while (g_ready == 0) { } }
    __syncthreads();
    __threadfence();

    int ex = s - v + (w ? ws[w - 1] : 0) + g_boff[b];
    if (i < NN) { g_off[i] = ex; g_cur[i] = ex; }
}

__global__ void scatter_kernel(const int* __restrict__ src,
                               const int* __restrict__ dst,
                               const int* __restrict__ ea) {
    int e = blockIdx.x * blockDim.x + threadIdx.x;
    if (e >= EE) return;
    int d = dst[e];
    int code = (ea[e * 3 + 0] * 5 + ea[e * 3 + 1]) * 5 + ea[e * 3 + 2];
    int pos = atomicAdd(&g_cur[d], 1);
    g_csr2[pos] = make_int2((src[e] << 7) | code, d);
}

// ---------------------------------------------------------------------------
// Aggregation (unchanged): warp per 128-edge chunk, 2-stage cp.async.
// ---------------------------------------------------------------------------
#define CP_ASYNC8(sa, ga) \
    asm volatile("cp.async.ca.shared.global [%0], [%1], 8;" :: "r"(sa), "l"(ga))
#define CP_COMMIT() asm volatile("cp.async.commit_group;" ::: "memory")
#define CP_WAIT(n)  asm volatile("cp.async.wait_group " #n ";" ::: "memory")

__device__ __forceinline__ void issue_batch(int ebase, int lane, uint2* sbuf, int2& qn) {
    qn = g_csr2[ebase + (lane & 7)];
#pragma unroll
    for (int j = 0; j < PF; j++) {
        int sx = __shfl_sync(0xffffffffu, qn.x, j) >> 7;
        unsigned sa = (unsigned)__cvta_generic_to_shared(&sbuf[j * 32 + lane]);
        CP_ASYNC8(sa, &g_xh[sx * 32 + lane]);
    }
    CP_COMMIT();
}

__device__ __forceinline__ void consume_batch(int lane, const uint2* sbuf, int2 qc,
                                              float4& acc, int& cur) {
    const uint2* ch2 = (const uint2*)g_ch;
    const __half2 z = __float2half2_rn(0.f);
#pragma unroll
    for (int j = 0; j < PF; j++) {
        int wv = __shfl_sync(0xffffffffu, qc.x, j);
        int d  = __shfl_sync(0xffffffffu, qc.y, j);
        uint2 xv = sbuf[j * 32 + lane];
        uint2 cv = ch2[(wv & 127) * 32 + lane];
        __half2 m0 = __hmax2(__hadd2(*(__half2*)&xv.x, *(__half2*)&cv.x), z);
        __half2 m1 = __hmax2(__hadd2(*(__half2*)&xv.y, *(__half2*)&cv.y), z);
        float2 f0 = __half22float2(m0);
        float2 f1 = __half22float2(m1);
        if (d != cur) {
            if (cur >= 0) atomicAdd(&((float4*)g_h)[cur * 32 + lane], acc);
            cur = d;
            acc = make_float4(f0.x, f0.y, f1.x, f1.y);
        } else {
            acc.x += f0.x; acc.y += f0.y; acc.z += f1.x; acc.w += f1.y;
        }
    }
}

__global__ void __launch_bounds__(256) agg_kernel() {
    __shared__ uint2 buf[8][2][PF * 32];
    int wid = threadIdx.x >> 5, lane = threadIdx.x & 31;
    int wrp = blockIdx.x * 8 + wid;
    if (wrp >= NWRP) return;
    const int base = wrp * CHUNK;

    uint2* sp[2] = { buf[wid][0], buf[wid][1] };
    int2 qs[2];
    float4 acc = make_float4(0, 0, 0, 0);
    int cur = -1;

    issue_batch(base, lane, sp[0], qs[0]);
#pragma unroll
    for (int b = 0; b < NB; b++) {
        if (b < NB - 1) {
            issue_batch(base + (b + 1) * PF, lane, sp[(b + 1) & 1], qs[(b + 1) & 1]);
            CP_WAIT(1);
        } else {
            CP_WAIT(0);
        }
        consume_batch(lane, sp[b & 1], qs[b & 1], acc, cur);
    }
    if (cur >= 0) atomicAdd(&((float4*)g_h)[cur * 32 + lane], acc);
}

// ---------------------------------------------------------------------------
// Split-precision HMMA GEMM: A@B via Ah@Bh + Ah@Bl + Al@Bh (fp16 hi+lo pairs,
// fp32 accum). Dropped Al@Bl term is ~2^-22 relative -> fp32-grade accuracy.
// PASS 1: in=g_h, out=g_h1, BN stats. PASS 2: in=relu(BN(g_h1)), out=d_out.
// smem: A_hi/A_lo [64][136]h, Bt_hi/Bt_lo [128][136]h  (102 KB total).
// ---------------------------------------------------------------------------
#define AP 136
#define APB (AP * 2)
#define A_HI_OFF 0
#define A_LO_OFF (64 * APB)                 // 17408
#define BT_HI_OFF (2 * 64 * APB)            // 34816
#define BT_LO_OFF (BT_HI_OFF + 128 * APB)   // 69632
#define G_HMMA_SMEM (BT_LO_OFF + 128 * APB) // 104448

#define LDSM_X4(r0, r1, r2, r3, a) \
    asm volatile("ldmatrix.sync.aligned.m8n8.x4.shared.b16 {%0,%1,%2,%3}, [%4];" \
                 : "=r"(r0), "=r"(r1), "=r"(r2), "=r"(r3) : "r"(a))
#define MMA16816(d0, d1, d2, d3, a0, a1, a2, a3, b0, b1) \
    asm volatile("mma.sync.aligned.m16n8k16.row.col.f32.f16.f16.f32 " \
                 "{%0,%1,%2,%3},{%4,%5,%6,%7},{%8,%9},{%0,%1,%2,%3};" \
                 : "+f"(d0), "+f"(d1), "+f"(d2), "+f"(d3) \
                 : "r"(a0), "r"(a1), "r"(a2), "r"(a3), "r"(b0), "r"(b1))

__device__ __forceinline__ void split2(float2 v, __half2& hi, __half2& lo) {
    hi = __float22half2_rn(v);
    float2 hf = __half22float2(hi);
    lo = __float22half2_rn(make_float2(v.x - hf.x, v.y - hf.y));
}

template <int PASS>
__global__ __launch_bounds__(128)
void gemm_hmma(const float* __restrict__ Wg, const float* __restrict__ bias,
               float* __restrict__ outp,
               const float* __restrict__ gamma, const float* __restrict__ beta) {
    extern __shared__ char shm[];
    __shared__ float ssum[128], ssq[128], sbias[128], sa[128], sb[128];
    const int t = threadIdx.x, lane = t & 31, w = t >> 5;
    const int rowbase = blockIdx.x * 64;

    sbias[t] = bias[t];
    if (PASS == 1) { ssum[t] = 0.f; ssq[t] = 0.f; }
    if (PASS == 2) {
        const float inv = 1.0f / (float)NN;
        float mean = g_sum[t] * inv;
        float var  = g_sumsq[t] * inv - mean * mean;
        float s = gamma[t] * rsqrtf(var + 1e-5f);
        sa[t] = s;
        sb[t] = beta[t] - mean * s;
    }
    __syncthreads();

    // Stage A hi/lo (64 rows x 128 cols)
    {
        const float2* in2 = (PASS == 1) ? (const float2*)g_h : (const float2*)g_h1;
#pragma unroll
        for (int j = 0; j < 32; j++) {
            int idx2 = t + j * 128;
            int row = idx2 >> 6, c2 = idx2 & 63;
            int gr = rowbase + row;
            float2 v = (gr < NN) ? in2[gr * 64 + c2] : make_float2(0.f, 0.f);
            if (PASS == 2) {
                float2 aa = *(const float2*)&sa[c2 * 2];
                float2 bb = *(const float2*)&sb[c2 * 2];
                v.x = fmaxf(fmaf(v.x, aa.x, bb.x), 0.f);
                v.y = fmaxf(fmaf(v.y, aa.y, bb.y), 0.f);
            }
            __half2 hi, lo;
            split2(v, hi, lo);
            *(__half2*)(shm + A_HI_OFF + row * APB + c2 * 4) = hi;
            *(__half2*)(shm + A_LO_OFF + row * APB + c2 * 4) = lo;
        }
    }
    // Stage Bt hi/lo: W^T [n][k], thread t owns n = t
    {
#pragma unroll 8
        for (int k2 = 0; k2 < 64; k2++) {
            float2 v = make_float2(Wg[(2 * k2) * 128 + t], Wg[(2 * k2 + 1) * 128 + t]);
            __half2 hi, lo;
            split2(v, hi, lo);
            *(__half2*)(shm + BT_HI_OFF + t * APB + k2 * 4) = hi;
            *(__half2*)(shm + BT_LO_OFF + t * APB + k2 * 4) = lo;
        }
    }
    __syncthreads();

    const unsigned base = (unsigned)__cvta_generic_to_shared(shm);
    const unsigned a_row_off = (unsigned)((w * 16 + ((lane >> 3) & 1) * 8 + (lane & 7)) * APB
                                          + (((lane >> 4) & 1) * 8) * 2);
    const unsigned b_row_off = (unsigned)((((lane >> 4) & 1) * 8 + (lane & 7)) * APB);
    const unsigned b_k_off   = (unsigned)((((lane >> 3) & 1) * 8) * 2);

    float d[16][4];
#pragma unroll
    for (int nt = 0; nt < 16; nt++)
#pragma unroll
        for (int i = 0; i < 4; i++) d[nt][i] = 0.f;

#pragma unroll
    for (int ks = 0; ks < 8; ks++) {
        unsigned kb = (unsigned)(ks * 32);
        unsigned ah0, ah1, ah2, ah3, al0, al1, al2, al3;
        LDSM_X4(ah0, ah1, ah2, ah3, base + A_HI_OFF + a_row_off + kb);
        LDSM_X4(al0, al1, al2, al3, base + A_LO_OFF + a_row_off + kb);
#pragma unroll
        for (int j = 0; j < 8; j++) {
            unsigned off = (unsigned)(j * 16 * APB) + b_row_off + b_k_off + kb;
            unsigned bh0, bh1, bh2, bh3, bl0, bl1, bl2, bl3;
            LDSM_X4(bh0, bh1, bh2, bh3, base + BT_HI_OFF + off);
            LDSM_X4(bl0, bl1, bl2, bl3, base + BT_LO_OFF + off);
            MMA16816(d[2*j][0], d[2*j][1], d[2*j][2], d[2*j][3], ah0, ah1, ah2, ah3, bh0, bh1);
            MMA16816(d[2*j+1][0], d[2*j+1][1], d[2*j+1][2], d[2*j+1][3], ah0, ah1, ah2, ah3, bh2, bh3);
            MMA16816(d[2*j][0], d[2*j][1], d[2*j][2], d[2*j][3], ah0, ah1, ah2, ah3, bl0, bl1);
            MMA16816(d[2*j+1][0], d[2*j+1][1], d[2*j+1][2], d[2*j+1][3], ah0, ah1, ah2, ah3, bl2, bl3);
            MMA16816(d[2*j][0], d[2*j][1], d[2*j][2], d[2*j][3], al0, al1, al2, al3, bh0, bh1);
            MMA16816(d[2*j+1][0], d[2*j+1][1], d[2*j+1][2], d[2*j+1][3], al0, al1, al2, al3, bh2, bh3);
        }
    }

    // Epilogue
    const int r_lo = rowbase + w * 16 + (lane >> 2);
    const int r_hi = r_lo + 8;
    bool v_lo = (r_lo < NN), v_hi = (r_hi < NN);
    float2* out2 = (PASS == 1) ? (float2*)g_h1 : (float2*)outp;

#pragma unroll
    for (int nt = 0; nt < 16; nt++) {
        int col = nt * 8 + (lane & 3) * 2;
        float b0 = sbias[col], b1 = sbias[col + 1];
        float o0 = d[nt][0] + b0, o1 = d[nt][1] + b1;
        float o2 = d[nt][2] + b0, o3 = d[nt][3] + b1;
        if (v_lo) out2[(r_lo * 128 + col) >> 1] = make_float2(o0, o1);
        if (v_hi) out2[(r_hi * 128 + col) >> 1] = make_float2(o2, o3);
        if (PASS == 1) {
            float ts0 = (v_lo ? o0 : 0.f) + (v_hi ? o2 : 0.f);
            float ts1 = (v_lo ? o1 : 0.f) + (v_hi ? o3 : 0.f);
            float tq0 = (v_lo ? o0 * o0 : 0.f) + (v_hi ? o2 * o2 : 0.f);
            float tq1 = (v_lo ? o1 * o1 : 0.f) + (v_hi ? o3 * o3 : 0.f);
#pragma unroll
            for (int o = 16; o >= 4; o >>= 1) {
                ts0 += __shfl_down_sync(0xffffffffu, ts0, o);
                ts1 += __shfl_down_sync(0xffffffffu, ts1, o);
                tq0 += __shfl_down_sync(0xffffffffu, tq0, o);
                tq1 += __shfl_down_sync(0xffffffffu, tq1, o);
            }
            if (lane < 4) {
                atomicAdd(&ssum[col], ts0);
                atomicAdd(&ssum[col + 1], ts1);
                atomicAdd(&ssq[col], tq0);
                atomicAdd(&ssq[col + 1], tq1);
            }
        }
    }
    if (PASS == 1) {
        __syncthreads();
        atomicAdd(&g_sum[t],   ssum[t]);
        atomicAdd(&g_sumsq[t], ssq[t]);
    }
}

// ---------------------------------------------------------------------------
extern "C" void kernel_launch(void* const* d_in, const int* in_sizes, int n_in,
                              void* d_out, int out_size) {
    const float* x     = (const float*)d_in[0];
    const int*   ea    = (const int*)  d_in[1];
    const int*   src   = (const int*)  d_in[2];
    const int*   dst   = (const int*)  d_in[3];
    const float* bond  = (const float*)d_in[4];
    const float* eps   = (const float*)d_in[5];
    const float* W1    = (const float*)d_in[6];
    const float* b1    = (const float*)d_in[7];
    const float* gamma = (const float*)d_in[8];
    const float* beta  = (const float*)d_in[9];
    const float* W2    = (const float*)d_in[10];
    const float* b2    = (const float*)d_in[11];

    cudaFuncSetAttribute(gemm_hmma<1>, cudaFuncAttributeMaxDynamicSharedMemorySize, G_HMMA_SMEM);
    cudaFuncSetAttribute(gemm_hmma<2>, cudaFuncAttributeMaxDynamicSharedMemorySize, G_HMMA_SMEM);

    fused_setup<<<(NN * 32 + 255) / 256, 256>>>((const float4*)x, bond, dst, eps);
    scan_kernel<<<NBLK, SCAN_B>>>();
    scatter_kernel<<<(EE + 255) / 256, 256>>>(src, dst, ea);
    agg_kernel<<<(NWRP + 7) / 8, 256>>>();
    gemm_hmma<1><<<(NN + 63) / 64, 128, G_HMMA_SMEM>>>(W1, b1, nullptr, nullptr, nullptr);
    gemm_hmma<2><<<(NN + 63) / 64, 128, G_HMMA_SMEM>>>(W2, b2, (float*)d_out, gamma, beta);
}